// round 11
// baseline (speedup 1.0000x reference)
#include <cuda_runtime.h>
#include <stdint.h>

// MessagePassing: out[dst[e]] += x[src[e]], N=100000, E=1600000, D=32 fp32.
// edge_index int32 [2, E]: row 0 = src, row 1 = dst.
//
// Partition pipeline v3:
//   B) single-pass scatter into 16 SUB-CURSORS per 128-node partition
//      (12512 atomic addresses -> ~128 ops/address: no serialization;
//      sub = lane&15 -> no intra-warp same-address replays). Packed word
//      (src<<7 | dst&127). Overflow -> global list.
//   C) 1 CTA per 128-node partition (782 CTAs, ~27KB smem -> high occ):
//      compact the 16 sub-segments into smem, counting-sort by node,
//      node-major register accumulation (8 lanes/node, MLP=8, tree adds),
//      one plain 128B store per node (no out memset needed).
//   D) rare overflow edges applied via RED after C.

#define D_FEAT     32
#define CHUNKS     8
#define PART_BITS  7
#define PART_SIZE  128        // nodes per partition
#define MAX_NODES  131072
#define MAX_PARTS  (MAX_NODES >> PART_BITS)   // 1024
#define SUBS       16
#define SUB_CAP    192        // mean 128 (Poisson) + ~5.7 sigma
#define PCAP       (SUBS * SUB_CAP)           // 3072 words per partition
#define OVF_CAP    (1u << 21)

__device__ unsigned g_cursor[MAX_PARTS * SUBS];           // 64 KB
__device__ unsigned g_ovf_cnt;
__device__ unsigned g_buckets[(long)MAX_PARTS * PCAP];    // 12.6 MB
__device__ int2     g_ovf[OVF_CAP];

__device__ __forceinline__ void red_add_v4(float* p, float4 v) {
    asm volatile("red.global.add.v4.f32 [%0], {%1, %2, %3, %4};"
                 :: "l"(p), "f"(v.x), "f"(v.y), "f"(v.z), "f"(v.w)
                 : "memory");
}

__device__ __forceinline__ float4 f4add(float4 a, float4 b) {
    return make_float4(a.x + b.x, a.y + b.y, a.z + b.z, a.w + b.w);
}

// ---------------- Phase B: sub-cursor scatter ----------------
__device__ __forceinline__ void part_one(int s, int d, unsigned sub) {
    unsigned part = (unsigned)d >> PART_BITS;
    unsigned cidx = part * SUBS + sub;
    unsigned pos  = atomicAdd(&g_cursor[cidx], 1u);
    if (pos < SUB_CAP) {
        g_buckets[(long)cidx * SUB_CAP + pos] =
            ((unsigned)s << PART_BITS) | ((unsigned)d & (PART_SIZE - 1));
    } else {
        unsigned o = atomicAdd(&g_ovf_cnt, 1u);
        if (o < OVF_CAP) g_ovf[o] = make_int2(s, d);
    }
}

__global__ void mp_part_kernel(const int* __restrict__ src,
                               const int* __restrict__ dst,
                               long n_edges) {
    long t  = (long)blockIdx.x * blockDim.x + threadIdx.x;
    unsigned sub = threadIdx.x & (SUBS - 1);   // lane-derived: no intra-warp
    long e0 = t * 8;                           // same-address atomic replays
    if (e0 >= n_edges) return;
    if (e0 + 8 <= n_edges) {
        int4 sa = __ldg((const int4*)(src + e0));
        int4 sb = __ldg((const int4*)(src + e0 + 4));
        int4 da = __ldg((const int4*)(dst + e0));
        int4 db = __ldg((const int4*)(dst + e0 + 4));
        part_one(sa.x, da.x, sub); part_one(sa.y, da.y, sub);
        part_one(sa.z, da.z, sub); part_one(sa.w, da.w, sub);
        part_one(sb.x, db.x, sub); part_one(sb.y, db.y, sub);
        part_one(sb.z, db.z, sub); part_one(sb.w, db.w, sub);
    } else {
        for (long e = e0; e < n_edges; ++e)
            part_one(__ldg(&src[e]), __ldg(&dst[e]), sub);
    }
}

// ---------------- Phase C: per-partition sort + accumulate ----------------
#define C_THREADS 256

__global__ void __launch_bounds__(C_THREADS)
mp_agg_kernel(const float4* __restrict__ x,
              float4* __restrict__ out,
              int n_nodes) {
    __shared__ unsigned s_words[PCAP];     // 12 KB
    __shared__ unsigned s_sorted[PCAP];    // 12 KB
    __shared__ unsigned s_hist[PART_SIZE];
    __shared__ unsigned s_scan[PART_SIZE];
    __shared__ unsigned s_cur[PART_SIZE];
    __shared__ unsigned s_pref[SUBS + 1];

    int p   = blockIdx.x;
    int tid = threadIdx.x;

    if (tid < PART_SIZE) s_hist[tid] = 0;

    // Sub-segment counts -> serial prefix (16 entries, thread 0).
    if (tid == 0) {
        unsigned acc = 0;
        s_pref[0] = 0;
        #pragma unroll
        for (int sb = 0; sb < SUBS; ++sb) {
            unsigned c = g_cursor[p * SUBS + sb];
            if (c > SUB_CAP) c = SUB_CAP;
            acc += c;
            s_pref[sb + 1] = acc;
        }
    }
    __syncthreads();

    // Compact sub-segments into s_words + histogram by local node id.
    #pragma unroll
    for (int sb = 0; sb < SUBS; ++sb) {
        int lo = (int)s_pref[sb];
        int cs = (int)s_pref[sb + 1] - lo;
        const unsigned* bucket =
            g_buckets + (long)(p * SUBS + sb) * SUB_CAP;
        for (int i = tid; i < cs; i += C_THREADS) {
            unsigned w = __ldg(&bucket[i]);
            s_words[lo + i] = w;
            atomicAdd(&s_hist[w & (PART_SIZE - 1)], 1u);
        }
    }
    __syncthreads();

    int cnt = (int)s_pref[SUBS];

    // Inclusive Hillis-Steele scan over 128 entries (threads < 128 active).
    unsigned v = 0;
    if (tid < PART_SIZE) { v = s_hist[tid]; s_scan[tid] = v; }
    __syncthreads();
    #pragma unroll
    for (int dshift = 1; dshift < PART_SIZE; dshift <<= 1) {
        unsigned add = 0;
        if (tid < PART_SIZE && tid >= dshift) add = s_scan[tid - dshift];
        __syncthreads();
        if (tid < PART_SIZE) s_scan[tid] += add;
        __syncthreads();
    }
    if (tid < PART_SIZE) s_cur[tid] = s_scan[tid] - v;
    __syncthreads();

    // Counting-sort scatter (smem only).
    for (int i = tid; i < cnt; i += C_THREADS) {
        unsigned w = s_words[i];
        unsigned pos = atomicAdd(&s_cur[w & (PART_SIZE - 1)], 1u);
        s_sorted[pos] = w;
    }
    __syncthreads();

    // Node-major accumulate: 32 groups x 8 lanes; lane c owns chunk c.
    int grp = tid >> 3;
    int c   = tid & 7;
    for (int nl = grp; nl < PART_SIZE; nl += 32) {
        int n = (p << PART_BITS) + nl;
        if (n >= n_nodes) break;
        int k  = (int)s_hist[nl];
        int lo = (int)s_scan[nl] - k;
        float4 acc = make_float4(0.f, 0.f, 0.f, 0.f);
        int j = lo, end = lo + k;
        for (; j + 8 <= end; j += 8) {
            float4 a0 = __ldg(&x[(long)(s_sorted[j    ] >> PART_BITS) * CHUNKS + c]);
            float4 a1 = __ldg(&x[(long)(s_sorted[j + 1] >> PART_BITS) * CHUNKS + c]);
            float4 a2 = __ldg(&x[(long)(s_sorted[j + 2] >> PART_BITS) * CHUNKS + c]);
            float4 a3 = __ldg(&x[(long)(s_sorted[j + 3] >> PART_BITS) * CHUNKS + c]);
            float4 a4 = __ldg(&x[(long)(s_sorted[j + 4] >> PART_BITS) * CHUNKS + c]);
            float4 a5 = __ldg(&x[(long)(s_sorted[j + 5] >> PART_BITS) * CHUNKS + c]);
            float4 a6 = __ldg(&x[(long)(s_sorted[j + 6] >> PART_BITS) * CHUNKS + c]);
            float4 a7 = __ldg(&x[(long)(s_sorted[j + 7] >> PART_BITS) * CHUNKS + c]);
            float4 s03 = f4add(f4add(a0, a1), f4add(a2, a3));
            float4 s47 = f4add(f4add(a4, a5), f4add(a6, a7));
            acc = f4add(acc, f4add(s03, s47));
        }
        if (j + 4 <= end) {
            float4 a0 = __ldg(&x[(long)(s_sorted[j    ] >> PART_BITS) * CHUNKS + c]);
            float4 a1 = __ldg(&x[(long)(s_sorted[j + 1] >> PART_BITS) * CHUNKS + c]);
            float4 a2 = __ldg(&x[(long)(s_sorted[j + 2] >> PART_BITS) * CHUNKS + c]);
            float4 a3 = __ldg(&x[(long)(s_sorted[j + 3] >> PART_BITS) * CHUNKS + c]);
            acc = f4add(acc, f4add(f4add(a0, a1), f4add(a2, a3)));
            j += 4;
        }
        for (; j < end; ++j)
            acc = f4add(acc, __ldg(&x[(long)(s_sorted[j] >> PART_BITS) * CHUNKS + c]));
        out[(long)n * CHUNKS + c] = acc;   // plain store: no memset needed
    }
}

// ---------------- Phase D: rare overflow edges ----------------
__global__ void mp_ovf_kernel(const float4* __restrict__ x,
                              float* __restrict__ out) {
    unsigned cnt = g_ovf_cnt;
    if (cnt > OVF_CAP) cnt = OVF_CAP;
    for (unsigned i = blockIdx.x * blockDim.x + threadIdx.x; i < cnt;
         i += gridDim.x * blockDim.x) {
        int2 e = g_ovf[i];
        #pragma unroll
        for (int c = 0; c < CHUNKS; ++c)
            red_add_v4(out + (long)e.y * D_FEAT + c * 4,
                       __ldg(&x[(long)e.x * CHUNKS + c]));
    }
}

// ---------------- Fallback: edge-centric RED (R8) ----------------
__global__ void mp_scatter_kernel(const float4* __restrict__ x,
                                  const int* __restrict__ src,
                                  const int* __restrict__ dst,
                                  float* __restrict__ out,
                                  long n_edges) {
    long t = (long)blockIdx.x * blockDim.x + threadIdx.x;
    long e = t >> 3;
    int  c = (int)(t & 7);
    if (e >= n_edges) return;
    int s = __ldg(&src[e]);
    int d = __ldg(&dst[e]);
    float4 v = __ldg(&x[(long)s * CHUNKS + c]);
    red_add_v4(out + (long)d * D_FEAT + c * 4, v);
}

extern "C" void kernel_launch(void* const* d_in, const int* in_sizes, int n_in,
                              void* d_out, int out_size) {
    const float4* x   = (const float4*)d_in[0];
    const int*    ei  = (const int*)d_in[1];
    long n_edges = (long)in_sizes[1] / 2;
    const int* src = ei;
    const int* dst = ei + n_edges;
    float* out = (float*)d_out;
    int n_nodes = in_sizes[0] / D_FEAT;
    int threads = 256;

    if (n_nodes > MAX_NODES || n_edges > (long)OVF_CAP) {
        cudaMemsetAsync(d_out, 0, (size_t)out_size * sizeof(float), 0);
        long total = n_edges * CHUNKS;
        long blocks = (total + threads - 1) / threads;
        mp_scatter_kernel<<<(unsigned)blocks, threads>>>(x, src, dst, out, n_edges);
        return;
    }

    void* cur_ptr = nullptr; cudaGetSymbolAddress(&cur_ptr, g_cursor);
    void* ovf_ptr = nullptr; cudaGetSymbolAddress(&ovf_ptr, g_ovf_cnt);
    cudaMemsetAsync(cur_ptr, 0, sizeof(unsigned) * MAX_PARTS * SUBS, 0);
    cudaMemsetAsync(ovf_ptr, 0, sizeof(unsigned), 0);

    // Phase B: sub-cursor scatter (8 edges/thread, 782 CTAs).
    {
        long groups = (n_edges + 7) / 8;
        long blocks = (groups + threads - 1) / threads;
        mp_part_kernel<<<(unsigned)blocks, threads>>>(src, dst, n_edges);
    }
    // Phase C: one CTA per 128-node partition (782 CTAs).
    {
        int parts = (n_nodes + PART_SIZE - 1) / PART_SIZE;
        mp_agg_kernel<<<parts, C_THREADS>>>(x, (float4*)out, n_nodes);
    }
    // Phase D: overflow (normally empty).
    mp_ovf_kernel<<<32, 256>>>(x, out);
}

// round 12
// speedup vs baseline: 1.5099x; 1.5099x over previous
#include <cuda_runtime.h>
#include <stdint.h>

// MessagePassing: out[dst[e]] += x[src[e]], N=100000, E=1600000, D=32 fp32.
// edge_index int32 [2, E]: row 0 = src, row 1 = dst.
//
// Edge-centric scatter at the measured LTS ceiling (~423MB L2 sector traffic
// @ ~11.2TB/s): 8 lanes per edge-group cover one 128B feature row
// (float4/lane); each group processes 16 edges with int4-vectorized index
// loads and all 16 gathers issued before any RED (MLP=16). Scatter via
// red.global.add.v4.f32 (fire-and-forget RED.128). Output zeroed via a
// cudaMemsetAsync graph node.

#define D_FEAT 32
#define CHUNKS 8    // D_FEAT / 4
#define EPT    16   // edges per thread-group

__device__ __forceinline__ void red_add_v4(float* p, float4 v) {
    asm volatile("red.global.add.v4.f32 [%0], {%1, %2, %3, %4};"
                 :: "l"(p), "f"(v.x), "f"(v.y), "f"(v.z), "f"(v.w)
                 : "memory");
}

__global__ void mp_scatter_kernel(const float4* __restrict__ x,
                                  const int* __restrict__ src,
                                  const int* __restrict__ dst,
                                  float* __restrict__ out,
                                  long n_edges) {
    long t = (long)blockIdx.x * blockDim.x + threadIdx.x;
    long g = t >> 3;          // edge-group index
    int  c = (int)(t & 7);    // 16B chunk within the 128B feature row
    long e0 = g * EPT;
    if (e0 >= n_edges) return;

    if (e0 + EPT <= n_edges) {
        // Vectorized index loads: e0 is a multiple of 16 -> 16B aligned.
        int4 s0 = __ldg((const int4*)(src + e0));
        int4 s1 = __ldg((const int4*)(src + e0 + 4));
        int4 s2 = __ldg((const int4*)(src + e0 + 8));
        int4 s3 = __ldg((const int4*)(src + e0 + 12));
        int4 d0 = __ldg((const int4*)(dst + e0));
        int4 d1 = __ldg((const int4*)(dst + e0 + 4));
        int4 d2 = __ldg((const int4*)(dst + e0 + 8));
        int4 d3 = __ldg((const int4*)(dst + e0 + 12));

        // Batch all 16 gathers (MLP=16) before any RED.
        float4 v0  = __ldg(&x[(long)s0.x * CHUNKS + c]);
        float4 v1  = __ldg(&x[(long)s0.y * CHUNKS + c]);
        float4 v2  = __ldg(&x[(long)s0.z * CHUNKS + c]);
        float4 v3  = __ldg(&x[(long)s0.w * CHUNKS + c]);
        float4 v4  = __ldg(&x[(long)s1.x * CHUNKS + c]);
        float4 v5  = __ldg(&x[(long)s1.y * CHUNKS + c]);
        float4 v6  = __ldg(&x[(long)s1.z * CHUNKS + c]);
        float4 v7  = __ldg(&x[(long)s1.w * CHUNKS + c]);
        float4 v8  = __ldg(&x[(long)s2.x * CHUNKS + c]);
        float4 v9  = __ldg(&x[(long)s2.y * CHUNKS + c]);
        float4 v10 = __ldg(&x[(long)s2.z * CHUNKS + c]);
        float4 v11 = __ldg(&x[(long)s2.w * CHUNKS + c]);
        float4 v12 = __ldg(&x[(long)s3.x * CHUNKS + c]);
        float4 v13 = __ldg(&x[(long)s3.y * CHUNKS + c]);
        float4 v14 = __ldg(&x[(long)s3.z * CHUNKS + c]);
        float4 v15 = __ldg(&x[(long)s3.w * CHUNKS + c]);

        int co = c * 4;
        red_add_v4(out + (long)d0.x * D_FEAT + co, v0);
        red_add_v4(out + (long)d0.y * D_FEAT + co, v1);
        red_add_v4(out + (long)d0.z * D_FEAT + co, v2);
        red_add_v4(out + (long)d0.w * D_FEAT + co, v3);
        red_add_v4(out + (long)d1.x * D_FEAT + co, v4);
        red_add_v4(out + (long)d1.y * D_FEAT + co, v5);
        red_add_v4(out + (long)d1.z * D_FEAT + co, v6);
        red_add_v4(out + (long)d1.w * D_FEAT + co, v7);
        red_add_v4(out + (long)d2.x * D_FEAT + co, v8);
        red_add_v4(out + (long)d2.y * D_FEAT + co, v9);
        red_add_v4(out + (long)d2.z * D_FEAT + co, v10);
        red_add_v4(out + (long)d2.w * D_FEAT + co, v11);
        red_add_v4(out + (long)d3.x * D_FEAT + co, v12);
        red_add_v4(out + (long)d3.y * D_FEAT + co, v13);
        red_add_v4(out + (long)d3.z * D_FEAT + co, v14);
        red_add_v4(out + (long)d3.w * D_FEAT + co, v15);
    } else {
        // Tail: scalar loop over remaining edges (not taken for E=1.6M).
        for (long e = e0; e < n_edges; ++e) {
            int s = __ldg(&src[e]);
            int d = __ldg(&dst[e]);
            float4 v = __ldg(&x[(long)s * CHUNKS + c]);
            red_add_v4(out + (long)d * D_FEAT + c * 4, v);
        }
    }
}

extern "C" void kernel_launch(void* const* d_in, const int* in_sizes, int n_in,
                              void* d_out, int out_size) {
    const float4* x   = (const float4*)d_in[0];
    const int*    ei  = (const int*)d_in[1];
    long n_edges = (long)in_sizes[1] / 2;      // edge_index has 2*E elements
    const int* src = ei;                       // row 0
    const int* dst = ei + n_edges;             // row 1
    float* out = (float*)d_out;

    // Zero the (poisoned) output via a memset node.
    cudaMemsetAsync(d_out, 0, (size_t)out_size * sizeof(float), 0);

    // Scatter-add: 8 lanes per edge-group, 16 edges per group.
    long groups = (n_edges + EPT - 1) / EPT;
    long total  = groups * 8;
    int threads = 256;
    long blocks = (total + threads - 1) / threads;
    mp_scatter_kernel<<<(unsigned)blocks, threads>>>(x, src, dst, out, n_edges);
}

// round 13
// speedup vs baseline: 1.5748x; 1.0430x over previous
#include <cuda_runtime.h>
#include <stdint.h>

// MessagePassing: out[dst[e]] += x[src[e]], N=100000, E=1600000, D=32 fp32.
// edge_index int32 [2, E]: row 0 = src, row 1 = dst.
//
// Edge-centric scatter at the measured LTS ceiling (~423MB L2 sector traffic
// @ ~11.2TB/s, the chip cap): 8 lanes per edge-group cover one 128B feature
// row (float4/lane); each group processes 8 edges with int4-vectorized index
// loads and all 8 gathers issued before any RED (MLP=8). Scatter via
// red.global.add.v4.f32 (fire-and-forget RED.128). Output zeroed via a
// cudaMemsetAsync graph node. EPT=8 keeps regs=32 -> occ ~84% (EPT=16
// measured worse: regs 40, occ 64%).

#define D_FEAT 32
#define CHUNKS 8   // D_FEAT / 4
#define EPT    8   // edges per thread-group (measured optimum)

__device__ __forceinline__ void red_add_v4(float* p, float4 v) {
    asm volatile("red.global.add.v4.f32 [%0], {%1, %2, %3, %4};"
                 :: "l"(p), "f"(v.x), "f"(v.y), "f"(v.z), "f"(v.w)
                 : "memory");
}

__global__ void __launch_bounds__(512)
mp_scatter_kernel(const float4* __restrict__ x,
                  const int* __restrict__ src,
                  const int* __restrict__ dst,
                  float* __restrict__ out,
                  long n_edges) {
    long t = (long)blockIdx.x * blockDim.x + threadIdx.x;
    long g = t >> 3;          // edge-group index
    int  c = (int)(t & 7);    // 16B chunk within the 128B feature row
    long e0 = g * EPT;
    if (e0 >= n_edges) return;

    if (e0 + EPT <= n_edges) {
        // Vectorized index loads: e0 is a multiple of 8 -> 16B aligned.
        int4 sa = __ldg((const int4*)(src + e0));
        int4 sb = __ldg((const int4*)(src + e0 + 4));
        int4 da = __ldg((const int4*)(dst + e0));
        int4 db = __ldg((const int4*)(dst + e0 + 4));

        // Batch all 8 gathers (MLP=8) before any RED.
        float4 v0 = __ldg(&x[(long)sa.x * CHUNKS + c]);
        float4 v1 = __ldg(&x[(long)sa.y * CHUNKS + c]);
        float4 v2 = __ldg(&x[(long)sa.z * CHUNKS + c]);
        float4 v3 = __ldg(&x[(long)sa.w * CHUNKS + c]);
        float4 v4 = __ldg(&x[(long)sb.x * CHUNKS + c]);
        float4 v5 = __ldg(&x[(long)sb.y * CHUNKS + c]);
        float4 v6 = __ldg(&x[(long)sb.z * CHUNKS + c]);
        float4 v7 = __ldg(&x[(long)sb.w * CHUNKS + c]);

        int co = c * 4;
        red_add_v4(out + (long)da.x * D_FEAT + co, v0);
        red_add_v4(out + (long)da.y * D_FEAT + co, v1);
        red_add_v4(out + (long)da.z * D_FEAT + co, v2);
        red_add_v4(out + (long)da.w * D_FEAT + co, v3);
        red_add_v4(out + (long)db.x * D_FEAT + co, v4);
        red_add_v4(out + (long)db.y * D_FEAT + co, v5);
        red_add_v4(out + (long)db.z * D_FEAT + co, v6);
        red_add_v4(out + (long)db.w * D_FEAT + co, v7);
    } else {
        // Tail: scalar loop over remaining edges (not taken for E=1.6M).
        for (long e = e0; e < n_edges; ++e) {
            int s = __ldg(&src[e]);
            int d = __ldg(&dst[e]);
            float4 v = __ldg(&x[(long)s * CHUNKS + c]);
            red_add_v4(out + (long)d * D_FEAT + c * 4, v);
        }
    }
}

extern "C" void kernel_launch(void* const* d_in, const int* in_sizes, int n_in,
                              void* d_out, int out_size) {
    const float4* x   = (const float4*)d_in[0];
    const int*    ei  = (const int*)d_in[1];
    long n_edges = (long)in_sizes[1] / 2;      // edge_index has 2*E elements
    const int* src = ei;                       // row 0
    const int* dst = ei + n_edges;             // row 1
    float* out = (float*)d_out;

    // Zero the (poisoned) output via a memset node.
    cudaMemsetAsync(d_out, 0, (size_t)out_size * sizeof(float), 0);

    // Scatter-add: 8 lanes per edge-group, 8 edges per group.
    long groups = (n_edges + EPT - 1) / EPT;
    long total  = groups * 8;
    int threads = 512;
    long blocks = (total + threads - 1) / threads;
    mp_scatter_kernel<<<(unsigned)blocks, threads>>>(x, src, dst, out, n_edges);
}